// round 5
// baseline (speedup 1.0000x reference)
#include <cuda_runtime.h>
#include <cuda_bf16.h>
#include <stdint.h>

#define B_ 512
#define T_ 32
#define D_ 512
#define M_ 1024
#define N_ (B_*T_)          // 16384
#define EPS_ 1e-5f

// ---------------- scratch (static device globals; no allocation) ----------------
__device__ __align__(16) __nv_bfloat16 g_a_bf[N_*D_];
__device__ __align__(16) __nv_bfloat16 g_v_bf[N_*D_];
__device__ __align__(16) __nv_bfloat16 g_e_bf[M_*D_];
__device__ float g_an[N_];
__device__ float g_vn[N_];
__device__ float g_en[M_];
__device__ __align__(16) __nv_bfloat16 g_sd_a[N_*M_];   // bf16 distances
__device__ __align__(16) __nv_bfloat16 g_sd_v[N_*M_];
__device__ __align__(16) __nv_bfloat16 g_adj_a[N_*M_];
__device__ __align__(16) __nv_bfloat16 g_adj_v[N_*M_];
__device__ float g_L_a[N_];                             // logsumexp(-sd) per row
__device__ float g_L_v[N_];
__device__ float g_rowsum[2*T_*B_];                     // sum_j exp(S[i,j]) unshifted
__device__ float g_diag[2*T_*B_];                       // exp(S[i,i])
__device__ double g_part[64];

// ---------------- reduction helpers ----------------
__device__ __forceinline__ float warpRedSum(float v){
  #pragma unroll
  for (int o=16;o>0;o>>=1) v += __shfl_xor_sync(0xffffffffu, v, o);
  return v;
}
__device__ __forceinline__ float warpRedMin(float v){
  #pragma unroll
  for (int o=16;o>0;o>>=1) v = fminf(v, __shfl_xor_sync(0xffffffffu, v, o));
  return v;
}
__device__ float blockSum(float v){
  __shared__ float sm[32]; __shared__ float res;
  int lane = threadIdx.x & 31, w = threadIdx.x >> 5, nw = blockDim.x >> 5;
  v = warpRedSum(v);
  if (!lane) sm[w] = v;
  __syncthreads();
  if (w == 0){
    float t = (lane < nw) ? sm[lane] : 0.f;
    t = warpRedSum(t);
    if (!lane) res = t;
  }
  __syncthreads();
  return res;
}
__device__ float blockMin(float v){
  __shared__ float sm[32]; __shared__ float res;
  int lane = threadIdx.x & 31, w = threadIdx.x >> 5, nw = blockDim.x >> 5;
  v = warpRedMin(v);
  if (!lane) sm[w] = v;
  __syncthreads();
  if (w == 0){
    float t = (lane < nw) ? sm[lane] : 3.4e38f;
    t = warpRedMin(t);
    if (!lane) res = t;
  }
  __syncthreads();
  return res;
}

// ---------------- zero rowsums (graph-replayed each call) ----------------
__global__ void k_zero(float* rs){
  rs[blockIdx.x*512 + threadIdx.x] = 0.f;
}

// ---------------- fused fp32->bf16 convert + row sq-norm (warp per row) ----------------
__global__ void k_prep(const float* __restrict__ x, __nv_bfloat16* __restrict__ xb,
                       float* __restrict__ nrm){
  int row = blockIdx.x*8 + (threadIdx.x >> 5);
  int lane = threadIdx.x & 31;
  const float4* src = (const float4*)(x + (size_t)row * D_);
  uint2* dst = (uint2*)(xb + (size_t)row * D_);
  float s = 0.f;
  #pragma unroll
  for (int i=0;i<4;i++){
    float4 f = src[lane + 32*i];
    s += f.x*f.x + f.y*f.y + f.z*f.z + f.w*f.w;
    __nv_bfloat162 h0 = __floats2bfloat162_rn(f.x, f.y);
    __nv_bfloat162 h1 = __floats2bfloat162_rn(f.z, f.w);
    uint2 o; o.x = *(unsigned*)&h0; o.y = *(unsigned*)&h1;
    dst[lane + 32*i] = o;
  }
  s = warpRedSum(s);
  if (!lane) nrm[row] = s;
}

// ---------------- HMMA mainloop machinery ----------------
__device__ __forceinline__ void cpa16(uint32_t s, const void* g){
  asm volatile("cp.async.cg.shared.global [%0], [%1], 16;" :: "r"(s), "l"(g));
}
__device__ __forceinline__ void ldmx4(uint32_t* r, uint32_t a){
  asm volatile("ldmatrix.sync.aligned.m8n8.x4.shared.b16 {%0,%1,%2,%3}, [%4];"
    : "=r"(r[0]), "=r"(r[1]), "=r"(r[2]), "=r"(r[3]) : "r"(a));
}
__device__ __forceinline__ void mma_bf16(float* c, const uint32_t* a, uint32_t b0, uint32_t b1){
  asm volatile("mma.sync.aligned.m16n8k16.row.col.f32.bf16.bf16.f32 "
    "{%0,%1,%2,%3}, {%4,%5,%6,%7}, {%8,%9}, {%0,%1,%2,%3};"
    : "+f"(c[0]), "+f"(c[1]), "+f"(c[2]), "+f"(c[3])
    : "r"(a[0]), "r"(a[1]), "r"(a[2]), "r"(a[3]), "r"(b0), "r"(b1));
}

// CTA tile 128(M) x 256(N), BK=64 bf16 (128B/row). 512 threads, 16 warps (2M x 8N),
// warp tile 64x32. 4-stage cp.async pipeline.
#define NBUF 4
#define ABYTES 16384          // 128 rows * 128B
#define STG 49152             // A(16K) + B(32K)
#define SMEM_DYN (NBUF*STG)   // 192KB

__device__ __forceinline__ void g_load(uint32_t sbase, int st, int ck,
                                       const char* Ab, const char* Bb,
                                       long ldab, long ldbb, int tid){
  uint32_t dA = sbase + (uint32_t)st * STG;
  uint32_t dB = dA + ABYTES;
  long koff = (long)ck * 128;
  #pragma unroll
  for (int i=0;i<2;i++){                 // A: 1024 x 16B chunks
    int idx = tid + (i<<9); int r = idx >> 3, c = idx & 7;
    uint32_t off = (uint32_t)(r*128 + ((c ^ (r&7))<<4));
    cpa16(dA + off, Ab + (long)r*ldab + koff + c*16);
  }
  #pragma unroll
  for (int i=0;i<4;i++){                 // B: 2048 x 16B chunks
    int idx = tid + (i<<9); int r = idx >> 3, c = idx & 7;
    uint32_t off = (uint32_t)(r*128 + ((c ^ (r&7))<<4));
    cpa16(dB + off, Bb + (long)r*ldbb + koff + c*16);
  }
  asm volatile("cp.async.commit_group;");
}

template<int KT>
__device__ __forceinline__ void g_main(uint32_t sbase, const char* Ab, const char* Bb,
                                       long ldab, long ldbb,
                                       float acc[4][4][4], int tid, int lane,
                                       int wmL, int wn){
  g_load(sbase, 0, 0, Ab, Bb, ldab, ldbb, tid);
  g_load(sbase, 1, 1, Ab, Bb, ldab, ldbb, tid);
  g_load(sbase, 2, 2, Ab, Bb, ldab, ldbb, tid);
  #pragma unroll 1
  for (int kt = 0; kt < KT; ++kt){
    if (kt+3 < KT) g_load(sbase, (kt+3)&3, kt+3, Ab, Bb, ldab, ldbb, tid);
    else asm volatile("cp.async.commit_group;");
    asm volatile("cp.async.wait_group 3;");
    __syncthreads();
    uint32_t aB = sbase + (uint32_t)(kt&3) * STG;
    uint32_t bB = aB + ABYTES;
    #pragma unroll
    for (int ks=0; ks<4; ++ks){
      uint32_t af[4][4], bfr[2][4];
      #pragma unroll
      for (int mi=0; mi<4; ++mi){
        int row = wmL + mi*16 + (lane & 15);
        int ch  = 2*ks + (lane >> 4);
        ldmx4(af[mi], aB + (uint32_t)(row*128 + ((ch ^ (row&7))<<4)));
      }
      #pragma unroll
      for (int p=0; p<2; ++p){
        int row = wn + p*16 + ((lane>>4)<<3) + (lane&7);
        int ch  = 2*ks + ((lane>>3)&1);
        ldmx4(bfr[p], bB + (uint32_t)(row*128 + ((ch ^ (row&7))<<4)));
      }
      #pragma unroll
      for (int mi=0; mi<4; ++mi)
        #pragma unroll
        for (int p=0; p<2; ++p){
          mma_bf16(acc[mi][p*2],   af[mi], bfr[p][0], bfr[p][1]);
          mma_bf16(acc[mi][p*2+1], af[mi], bfr[p][2], bfr[p][3]);
        }
    }
    __syncthreads();
  }
}

// ---------------- GEMM1: sd = bf16(sqrt(max(rn+cn-2*A.E^T,0))), both modalities ----------------
__global__ void __launch_bounds__(512, 1)
k_g1(const __nv_bfloat16* __restrict__ A0, const __nv_bfloat16* __restrict__ A1,
     const __nv_bfloat16* __restrict__ E,
     __nv_bfloat16* __restrict__ C0, __nv_bfloat16* __restrict__ C1,
     const float* __restrict__ rn0, const float* __restrict__ rn1,
     const float* __restrict__ cn)
{
  extern __shared__ char dsm[];
  uint32_t sbase = (uint32_t)__cvta_generic_to_shared(dsm);
  const int tid = threadIdx.x, lane = tid & 31, warp = tid >> 5;
  const int wmL = (warp & 1) * 64, wn = (warp >> 1) * 32;
  const int z = blockIdx.z;
  const __nv_bfloat16* A = z ? A1 : A0;
  const float* rn = z ? rn1 : rn0;
  __nv_bfloat16* C = z ? C1 : C0;

  const char* Ab = (const char*)A + (long)blockIdx.y * 128 * 1024;
  const char* Bb = (const char*)E + (long)blockIdx.x * 256 * 1024;

  float acc[4][4][4];
  #pragma unroll
  for (int a=0;a<4;a++)
    #pragma unroll
    for (int b=0;b<4;b++)
      #pragma unroll
      for (int c=0;c<4;c++) acc[a][b][c]=0.f;

  g_main<8>(sbase, Ab, Bb, 1024, 1024, acc, tid, lane, wmL, wn);

  const int tr = lane >> 2, tc = (lane & 3) * 2;
  #pragma unroll
  for (int mi=0; mi<4; ++mi){
    int r0 = blockIdx.y*128 + wmL + mi*16 + tr;
    float rn0v = rn[r0], rn1v = rn[r0+8];
    #pragma unroll
    for (int ni=0; ni<4; ++ni){
      int col = blockIdx.x*256 + wn + ni*8 + tc;
      float c0 = cn[col], c1 = cn[col+1];
      float* a = acc[mi][ni];
      __nv_bfloat162 o0 = __floats2bfloat162_rn(
          sqrtf(fmaxf(fmaf(-2.f, a[0], rn0v + c0), 0.f)),
          sqrtf(fmaxf(fmaf(-2.f, a[1], rn0v + c1), 0.f)));
      __nv_bfloat162 o1 = __floats2bfloat162_rn(
          sqrtf(fmaxf(fmaf(-2.f, a[2], rn1v + c0), 0.f)),
          sqrtf(fmaxf(fmaf(-2.f, a[3], rn1v + c1), 0.f)));
      *(__nv_bfloat162*)&C[(long)r0*M_ + col] = o0;
      *(__nv_bfloat162*)&C[(long)(r0+8)*M_ + col] = o1;
    }
  }
}

// ---------------- softmax (both modalities, one grid): adj=softmax(-2sd), L=lse(-sd) ----------------
__global__ void k_softmax2(const __nv_bfloat16* __restrict__ sda,
                           const __nv_bfloat16* __restrict__ sdv,
                           __nv_bfloat16* __restrict__ adja,
                           __nv_bfloat16* __restrict__ adjv,
                           float* __restrict__ La, float* __restrict__ Lv){
  int which = blockIdx.x >> 14;
  int row = blockIdx.x & (N_-1);
  const __nv_bfloat16* sd = which ? sdv : sda;
  __nv_bfloat16* adj = which ? adjv : adja;
  float* L = which ? Lv : La;
  size_t base = (size_t)row * M_;
  int tid = threadIdx.x;
  uint2 pk = *(const uint2*)(sd + base + tid*4);
  __nv_bfloat162 p0 = *(__nv_bfloat162*)&pk.x;
  __nv_bfloat162 p1 = *(__nv_bfloat162*)&pk.y;
  float v[4] = { __low2float(p0), __high2float(p0), __low2float(p1), __high2float(p1) };
  float vmin = fminf(fminf(v[0],v[1]), fminf(v[2],v[3]));
  float rmin = blockMin(vmin);
  float e[4]; float s1=0.f, s2=0.f;
  #pragma unroll
  for (int i=0;i<4;i++){ e[i] = __expf(rmin - v[i]); s1 += e[i]; s2 += e[i]*e[i]; }
  s1 = blockSum(s1);
  s2 = blockSum(s2);
  float i2 = 1.0f/s2;
  uint2 out;
  __nv_bfloat162 a0 = __floats2bfloat162_rn(e[0]*e[0]*i2, e[1]*e[1]*i2);
  __nv_bfloat162 a1 = __floats2bfloat162_rn(e[2]*e[2]*i2, e[3]*e[3]*i2);
  out.x = *(unsigned*)&a0; out.y = *(unsigned*)&a1;
  *(uint2*)(adj + base + tid*4) = out;
  if (tid == 0) L[row] = logf(s1) - rmin;
}

// ---------------- GEMM2 + fused loss epilogue ----------------
// S[i,j] = -(adj_i . sd_j) - L[j]; p = exp(S); accumulate rowsum + diagonal.
__global__ void __launch_bounds__(512, 1)
k_g2(const __nv_bfloat16* __restrict__ adjA, const __nv_bfloat16* __restrict__ adjV,
     const __nv_bfloat16* __restrict__ sdA,  const __nv_bfloat16* __restrict__ sdV,
     const float* __restrict__ La, const float* __restrict__ Lv,
     float* __restrict__ rowsum, float* __restrict__ diag)
{
  extern __shared__ char dsm[];
  uint32_t sbase = (uint32_t)__cvta_generic_to_shared(dsm);
  const int tid = threadIdx.x, lane = tid & 31, warp = tid >> 5;
  const int wmL = (warp & 1) * 64, wn = (warp >> 1) * 32;
  const int pair = blockIdx.z >> 5, t = blockIdx.z & 31;
  const __nv_bfloat16* A = pair ? adjV : adjA;
  const __nv_bfloat16* Bm = pair ? sdA : sdV;
  const float* L = pair ? La : Lv;

  const char* Ab = (const char*)A + (long)t*2048 + (long)blockIdx.y * 128 * 65536;
  const char* Bb = (const char*)Bm + (long)t*2048 + (long)blockIdx.x * 256 * 65536;

  float acc[4][4][4];
  #pragma unroll
  for (int a=0;a<4;a++)
    #pragma unroll
    for (int b=0;b<4;b++)
      #pragma unroll
      for (int c=0;c<4;c++) acc[a][b][c]=0.f;

  g_main<16>(sbase, Ab, Bb, 65536, 65536, acc, tid, lane, wmL, wn);

  // epilogue: p = exp(-acc - L[col]); per-row sums + diagonal
  const int tr = lane >> 2, tc = (lane & 3) * 2;
  const int batch = pair*T_ + t;
  float* dout = diag + (long)batch * B_;
  float rp[8];
  #pragma unroll
  for (int i=0;i<8;i++) rp[i]=0.f;
  #pragma unroll
  for (int mi=0; mi<4; ++mi){
    int rloc = wmL + mi*16 + tr;               // CTA-local row (for rp index use mi)
    int gi0 = blockIdx.y*128 + rloc;           // global row within batch [0,512)
    #pragma unroll
    for (int ni=0; ni<4; ++ni){
      int c0 = wn + ni*8 + tc;
      int gj = blockIdx.x*256 + c0;
      float L0 = L[(long)gj*T_ + t];
      float L1 = L[(long)(gj+1)*T_ + t];
      float* a = acc[mi][ni];
      float p00 = __expf(-a[0]-L0), p01 = __expf(-a[1]-L1);
      float p10 = __expf(-a[2]-L0), p11 = __expf(-a[3]-L1);
      rp[mi*2]   += p00 + p01;
      rp[mi*2+1] += p10 + p11;
      if (gj   == gi0)   dout[gi0]   = p00;
      if (gj+1 == gi0)   dout[gi0]   = p01;
      if (gj   == gi0+8) dout[gi0+8] = p10;
      if (gj+1 == gi0+8) dout[gi0+8] = p11;
    }
  }
  // reduce over 4 lanes sharing a row
  #pragma unroll
  for (int i=0;i<8;i++){
    rp[i] += __shfl_xor_sync(0xffffffffu, rp[i], 1);
    rp[i] += __shfl_xor_sync(0xffffffffu, rp[i], 2);
  }
  float* part = (float*)dsm;                   // [128][8]
  int ng = warp >> 1;
  if ((lane & 3) == 0){
    #pragma unroll
    for (int mi=0; mi<4; ++mi){
      int r = wmL + mi*16 + tr;
      part[r*8 + ng]     = rp[mi*2];
      part[(r+8)*8 + ng] = rp[mi*2+1];
    }
  }
  __syncthreads();
  if (tid < 128){
    float s = 0.f;
    #pragma unroll
    for (int k=0;k<8;k++) s += part[tid*8 + k];
    atomicAdd(&rowsum[(long)batch*B_ + blockIdx.y*128 + tid], s);
  }
}

// ---------------- loss partials and final mean ----------------
__global__ void k_loss2(const float* __restrict__ rs, const float* __restrict__ dg,
                        double* __restrict__ part){
  long base = (long)blockIdx.x * B_;
  float term = 0.f;
  #pragma unroll
  for (int h=0; h<2; ++h){
    long i = base + threadIdx.x + h*256;
    term += logf(rs[i] + 0.f) - logf(dg[i]);
  }
  float s = blockSum(term);
  if (threadIdx.x == 0) part[blockIdx.x] = (double)s;
}
__global__ void k_final(const double* __restrict__ part, float* __restrict__ out){
  double s = (threadIdx.x < 64) ? part[threadIdx.x] : 0.0;
  #pragma unroll
  for (int o=16;o>0;o>>=1) s += __shfl_xor_sync(0xffffffffu, s, o);
  __shared__ double sm[2];
  if ((threadIdx.x & 31) == 0) sm[threadIdx.x>>5] = s;
  __syncthreads();
  if (threadIdx.x == 0) out[0] = (float)((sm[0]+sm[1]) / 32768.0);
}

// ---------------- launch ----------------
extern "C" void kernel_launch(void* const* d_in, const int* in_sizes, int n_in,
                              void* d_out, int out_size)
{
  const float* a = (const float*)d_in[0];
  const float* v = (const float*)d_in[1];
  const float* e = (const float*)d_in[2];
  float* out = (float*)d_out;

  __nv_bfloat16 *pa, *pv, *pe, *psa, *psv, *paa, *pav;
  float *pan, *pvn, *pen, *pLa, *pLv, *prs, *pdg;
  double *ppt;
  cudaGetSymbolAddress((void**)&pa,  g_a_bf);
  cudaGetSymbolAddress((void**)&pv,  g_v_bf);
  cudaGetSymbolAddress((void**)&pe,  g_e_bf);
  cudaGetSymbolAddress((void**)&pan, g_an);
  cudaGetSymbolAddress((void**)&pvn, g_vn);
  cudaGetSymbolAddress((void**)&pen, g_en);
  cudaGetSymbolAddress((void**)&psa, g_sd_a);
  cudaGetSymbolAddress((void**)&psv, g_sd_v);
  cudaGetSymbolAddress((void**)&paa, g_adj_a);
  cudaGetSymbolAddress((void**)&pav, g_adj_v);
  cudaGetSymbolAddress((void**)&pLa, g_L_a);
  cudaGetSymbolAddress((void**)&pLv, g_L_v);
  cudaGetSymbolAddress((void**)&prs, g_rowsum);
  cudaGetSymbolAddress((void**)&pdg, g_diag);
  cudaGetSymbolAddress((void**)&ppt, g_part);

  cudaFuncSetAttribute(k_g1, cudaFuncAttributeMaxDynamicSharedMemorySize, SMEM_DYN);
  cudaFuncSetAttribute(k_g2, cudaFuncAttributeMaxDynamicSharedMemorySize, SMEM_DYN);

  // 0) zero the atomic rowsum accumulators
  k_zero<<<64, 512>>>(prs);

  // 1) fused convert + row sq-norms (warp per row)
  k_prep<<<N_/8, 256>>>(a, pa, pan);
  k_prep<<<N_/8, 256>>>(v, pv, pvn);
  k_prep<<<M_/8, 256>>>(e, pe, pen);

  // 2) distance GEMMs (both modalities in one grid) -> sd bf16
  dim3 g1(M_/256, N_/128, 2);
  k_g1<<<g1, 512, SMEM_DYN>>>(pa, pv, pe, psa, psv, pan, pvn, pen);

  // 3) dual-temperature softmax (both modalities in one grid)
  k_softmax2<<<2*N_, 256>>>(psa, psv, paa, pav, pLa, pLv);

  // 4) Scode GEMMs with fused exp/rowsum/diag epilogue (both pairs, all t)
  dim3 g2(B_/256, B_/128, 64);
  k_g2<<<g2, 512, SMEM_DYN>>>(paa, pav, psa, psv, pLa, pLv, prs, pdg);

  // 5) loss partials + final mean
  k_loss2<<<64, 256>>>(prs, pdg, ppt);
  k_final<<<1, 64>>>(ppt, out);
}

// round 6
// speedup vs baseline: 1.4576x; 1.4576x over previous
#include <cuda_runtime.h>
#include <cuda_bf16.h>
#include <stdint.h>

#define B_ 512
#define T_ 32
#define D_ 512
#define M_ 1024
#define N_ (B_*T_)          // 16384

// ---------------- scratch ----------------
__device__ __align__(16) __nv_bfloat16 g_a_bf[N_*D_];
__device__ __align__(16) __nv_bfloat16 g_v_bf[N_*D_];
__device__ __align__(16) __nv_bfloat16 g_e_bf[M_*D_];
__device__ float g_an[N_];
__device__ float g_vn[N_];
__device__ float g_en[M_];
__device__ __align__(16) __nv_bfloat16 g_sd_a[N_*M_];
__device__ __align__(16) __nv_bfloat16 g_sd_v[N_*M_];
__device__ __align__(16) __nv_bfloat16 g_adj_a[N_*M_];
__device__ __align__(16) __nv_bfloat16 g_adj_v[N_*M_];
__device__ float g_L_a[N_];
__device__ float g_L_v[N_];
__device__ float g_rowsum[2*T_*B_];
__device__ float g_diag[2*T_*B_];
__device__ double g_part[64];

// ---------------- reduction helpers ----------------
__device__ __forceinline__ float warpRedSum(float v){
  #pragma unroll
  for (int o=16;o>0;o>>=1) v += __shfl_xor_sync(0xffffffffu, v, o);
  return v;
}
__device__ __forceinline__ float warpRedMin(float v){
  #pragma unroll
  for (int o=16;o>0;o>>=1) v = fminf(v, __shfl_xor_sync(0xffffffffu, v, o));
  return v;
}
__device__ float blockSum(float v){
  __shared__ float sm[32]; __shared__ float res;
  int lane = threadIdx.x & 31, w = threadIdx.x >> 5, nw = blockDim.x >> 5;
  v = warpRedSum(v);
  if (!lane) sm[w] = v;
  __syncthreads();
  if (w == 0){
    float t = (lane < nw) ? sm[lane] : 0.f;
    t = warpRedSum(t);
    if (!lane) res = t;
  }
  __syncthreads();
  return res;
}
__device__ float blockMin(float v){
  __shared__ float sm[32]; __shared__ float res;
  int lane = threadIdx.x & 31, w = threadIdx.x >> 5, nw = blockDim.x >> 5;
  v = warpRedMin(v);
  if (!lane) sm[w] = v;
  __syncthreads();
  if (w == 0){
    float t = (lane < nw) ? sm[lane] : 3.4e38f;
    t = warpRedMin(t);
    if (!lane) res = t;
  }
  __syncthreads();
  return res;
}

__global__ void k_zero(float* rs){ rs[blockIdx.x*512 + threadIdx.x] = 0.f; }

// ---------------- merged convert + row sq-norm (warp per row, all 3 tensors) ----------------
__global__ void k_prep(const float* __restrict__ a, const float* __restrict__ v,
                       const float* __restrict__ e,
                       __nv_bfloat16* __restrict__ ab, __nv_bfloat16* __restrict__ vb,
                       __nv_bfloat16* __restrict__ eb,
                       float* __restrict__ an, float* __restrict__ vn,
                       float* __restrict__ en){
  int row = blockIdx.x*8 + (threadIdx.x >> 5);
  int lane = threadIdx.x & 31;
  const float* x; __nv_bfloat16* xb; float* nrm; int r;
  if (row < N_){ x=a; xb=ab; nrm=an; r=row; }
  else if (row < 2*N_){ x=v; xb=vb; nrm=vn; r=row-N_; }
  else { x=e; xb=eb; nrm=en; r=row-2*N_; }
  const float4* src = (const float4*)(x + (size_t)r * D_);
  uint2* dst = (uint2*)(xb + (size_t)r * D_);
  float s = 0.f;
  #pragma unroll
  for (int i=0;i<4;i++){
    float4 f = src[lane + 32*i];
    s += f.x*f.x + f.y*f.y + f.z*f.z + f.w*f.w;
    __nv_bfloat162 h0 = __floats2bfloat162_rn(f.x, f.y);
    __nv_bfloat162 h1 = __floats2bfloat162_rn(f.z, f.w);
    uint2 o; o.x = *(unsigned*)&h0; o.y = *(unsigned*)&h1;
    dst[lane + 32*i] = o;
  }
  s = warpRedSum(s);
  if (!lane) nrm[r] = s;
}

// ---------------- HMMA machinery ----------------
__device__ __forceinline__ void cpa16(uint32_t s, const void* g){
  asm volatile("cp.async.cg.shared.global [%0], [%1], 16;" :: "r"(s), "l"(g));
}
__device__ __forceinline__ void ldmx4(uint32_t* r, uint32_t a){
  asm volatile("ldmatrix.sync.aligned.m8n8.x4.shared.b16 {%0,%1,%2,%3}, [%4];"
    : "=r"(r[0]), "=r"(r[1]), "=r"(r[2]), "=r"(r[3]) : "r"(a));
}
__device__ __forceinline__ void mma_bf16(float* c, const uint32_t* a, uint32_t b0, uint32_t b1){
  asm volatile("mma.sync.aligned.m16n8k16.row.col.f32.bf16.bf16.f32 "
    "{%0,%1,%2,%3}, {%4,%5,%6,%7}, {%8,%9}, {%0,%1,%2,%3};"
    : "+f"(c[0]), "+f"(c[1]), "+f"(c[2]), "+f"(c[3])
    : "r"(a[0]), "r"(a[1]), "r"(a[2]), "r"(a[3]), "r"(b0), "r"(b1));
}

// CTA tile 128(M) x 256(N), BK=64 (128B rows). 256 threads, 8 warps (2M x 4N),
// warp tile 64x64. NBUF=4, single __syncthreads per K-chunk.
#define NBUF 4
#define ABYTES 16384
#define STG 49152
#define SMEM_DYN (NBUF*STG)   // 192KB

__device__ __forceinline__ void g_load(uint32_t sbase, int st, int ck,
                                       const char* Ab, const char* Bb,
                                       long ldab, long ldbb, int tid){
  uint32_t dA = sbase + (uint32_t)st * STG;
  uint32_t dB = dA + ABYTES;
  long koff = (long)ck * 128;
  #pragma unroll
  for (int i=0;i<4;i++){                 // A: 1024 x 16B
    int idx = tid + (i<<8); int r = idx >> 3, c = idx & 7;
    uint32_t off = (uint32_t)(r*128 + ((c ^ (r&7))<<4));
    cpa16(dA + off, Ab + (long)r*ldab + koff + c*16);
  }
  #pragma unroll
  for (int i=0;i<8;i++){                 // B: 2048 x 16B
    int idx = tid + (i<<8); int r = idx >> 3, c = idx & 7;
    uint32_t off = (uint32_t)(r*128 + ((c ^ (r&7))<<4));
    cpa16(dB + off, Bb + (long)r*ldbb + koff + c*16);
  }
  asm volatile("cp.async.commit_group;");
}

template<int KT>
__device__ __forceinline__ void g_main(uint32_t sbase, const char* Ab, const char* Bb,
                                       long ldab, long ldbb,
                                       float acc[4][8][4], int tid, int lane,
                                       int wm, int wn){
  g_load(sbase, 0, 0, Ab, Bb, ldab, ldbb, tid);
  g_load(sbase, 1, 1, Ab, Bb, ldab, ldbb, tid);
  g_load(sbase, 2, 2, Ab, Bb, ldab, ldbb, tid);
  #pragma unroll 1
  for (int kt = 0; kt < KT; ++kt){
    asm volatile("cp.async.wait_group 2;");
    __syncthreads();
    // buffer (kt+3)&3 == (kt-1)&3: reads of it finished in iter kt-1, proven by the sync above
    if (kt+3 < KT) g_load(sbase, (kt+3)&3, kt+3, Ab, Bb, ldab, ldbb, tid);
    else asm volatile("cp.async.commit_group;");
    uint32_t aB = sbase + (uint32_t)(kt&3) * STG;
    uint32_t bB = aB + ABYTES;
    #pragma unroll
    for (int ks=0; ks<4; ++ks){
      uint32_t af[4][4], bfr[4][4];
      #pragma unroll
      for (int mi=0; mi<4; ++mi){
        int row = wm + mi*16 + (lane & 15);
        int ch  = 2*ks + (lane >> 4);
        ldmx4(af[mi], aB + (uint32_t)(row*128 + ((ch ^ (row&7))<<4)));
      }
      #pragma unroll
      for (int p=0; p<4; ++p){
        int row = wn + p*16 + ((lane>>4)<<3) + (lane&7);
        int ch  = 2*ks + ((lane>>3)&1);
        ldmx4(bfr[p], bB + (uint32_t)(row*128 + ((ch ^ (row&7))<<4)));
      }
      #pragma unroll
      for (int mi=0; mi<4; ++mi)
        #pragma unroll
        for (int ni=0; ni<8; ++ni){
          const uint32_t* bp = bfr[ni>>1];
          uint32_t b0 = (ni&1) ? bp[2] : bp[0];
          uint32_t b1 = (ni&1) ? bp[3] : bp[1];
          mma_bf16(acc[mi][ni], af[mi], b0, b1);
        }
    }
  }
}

// ---------------- GEMM1: sd = bf16(sqrt(max(rn+cn-2*A.E^T,0))), both modalities ----------------
__global__ void __launch_bounds__(256, 1)
k_g1(const __nv_bfloat16* __restrict__ A0, const __nv_bfloat16* __restrict__ A1,
     const __nv_bfloat16* __restrict__ E,
     __nv_bfloat16* __restrict__ C0, __nv_bfloat16* __restrict__ C1,
     const float* __restrict__ rn0, const float* __restrict__ rn1,
     const float* __restrict__ cn)
{
  extern __shared__ char dsm[];
  uint32_t sbase = (uint32_t)__cvta_generic_to_shared(dsm);
  const int tid = threadIdx.x, lane = tid & 31, warp = tid >> 5;
  const int wm = (warp >> 2) * 64, wn = (warp & 3) * 64;
  const int z = blockIdx.z;
  const __nv_bfloat16* A = z ? A1 : A0;
  const float* rn = z ? rn1 : rn0;
  __nv_bfloat16* C = z ? C1 : C0;

  const char* Ab = (const char*)A + (long)blockIdx.y * 128 * 1024;
  const char* Bb = (const char*)E + (long)blockIdx.x * 256 * 1024;

  float acc[4][8][4];
  #pragma unroll
  for (int a=0;a<4;a++)
    #pragma unroll
    for (int b=0;b<8;b++)
      #pragma unroll
      for (int c=0;c<4;c++) acc[a][b][c]=0.f;

  g_main<8>(sbase, Ab, Bb, 1024, 1024, acc, tid, lane, wm, wn);

  const int tr = lane >> 2, tc = (lane & 3) * 2;
  #pragma unroll
  for (int mi=0; mi<4; ++mi){
    int r0 = blockIdx.y*128 + wm + mi*16 + tr;
    float rn0v = rn[r0], rn1v = rn[r0+8];
    #pragma unroll
    for (int ni=0; ni<8; ++ni){
      int col = blockIdx.x*256 + wn + ni*8 + tc;
      float c0 = cn[col], c1 = cn[col+1];
      float* a = acc[mi][ni];
      __nv_bfloat162 o0 = __floats2bfloat162_rn(
          sqrtf(fmaxf(fmaf(-2.f, a[0], rn0v + c0), 0.f)),
          sqrtf(fmaxf(fmaf(-2.f, a[1], rn0v + c1), 0.f)));
      __nv_bfloat162 o1 = __floats2bfloat162_rn(
          sqrtf(fmaxf(fmaf(-2.f, a[2], rn1v + c0), 0.f)),
          sqrtf(fmaxf(fmaf(-2.f, a[3], rn1v + c1), 0.f)));
      *(__nv_bfloat162*)&C[(long)r0*M_ + col] = o0;
      *(__nv_bfloat162*)&C[(long)(r0+8)*M_ + col] = o1;
    }
  }
}

// ---------------- softmax: adj = softmax(-2 sd), L = logsumexp(-sd) ----------------
__global__ void k_softmax2(const __nv_bfloat16* __restrict__ sda,
                           const __nv_bfloat16* __restrict__ sdv,
                           __nv_bfloat16* __restrict__ adja,
                           __nv_bfloat16* __restrict__ adjv,
                           float* __restrict__ La, float* __restrict__ Lv){
  int which = blockIdx.x >> 14;
  int row = blockIdx.x & (N_-1);
  const __nv_bfloat16* sd = which ? sdv : sda;
  __nv_bfloat16* adj = which ? adjv : adja;
  float* L = which ? Lv : La;
  size_t base = (size_t)row * M_;
  int tid = threadIdx.x;
  uint2 pk = *(const uint2*)(sd + base + tid*4);
  __nv_bfloat162 p0 = *(__nv_bfloat162*)&pk.x;
  __nv_bfloat162 p1 = *(__nv_bfloat162*)&pk.y;
  float v[4] = { __low2float(p0), __high2float(p0), __low2float(p1), __high2float(p1) };
  float vmin = fminf(fminf(v[0],v[1]), fminf(v[2],v[3]));
  float rmin = blockMin(vmin);
  float e[4]; float s1=0.f, s2=0.f;
  #pragma unroll
  for (int i=0;i<4;i++){ e[i] = __expf(rmin - v[i]); s1 += e[i]; s2 += e[i]*e[i]; }
  s1 = blockSum(s1);
  s2 = blockSum(s2);
  float i2 = 1.0f/s2;
  uint2 out;
  __nv_bfloat162 a0 = __floats2bfloat162_rn(e[0]*e[0]*i2, e[1]*e[1]*i2);
  __nv_bfloat162 a1 = __floats2bfloat162_rn(e[2]*e[2]*i2, e[3]*e[3]*i2);
  out.x = *(unsigned*)&a0; out.y = *(unsigned*)&a1;
  *(uint2*)(adj + base + tid*4) = out;
  if (tid == 0) L[row] = logf(s1) - rmin;
}

// ---------------- GEMM2 + fused loss epilogue ----------------
__global__ void __launch_bounds__(256, 1)
k_g2(const __nv_bfloat16* __restrict__ adjA, const __nv_bfloat16* __restrict__ adjV,
     const __nv_bfloat16* __restrict__ sdA,  const __nv_bfloat16* __restrict__ sdV,
     const float* __restrict__ La, const float* __restrict__ Lv,
     float* __restrict__ rowsum, float* __restrict__ diag)
{
  extern __shared__ char dsm[];
  uint32_t sbase = (uint32_t)__cvta_generic_to_shared(dsm);
  const int tid = threadIdx.x, lane = tid & 31, warp = tid >> 5;
  const int wm = (warp >> 2) * 64, wn = (warp & 3) * 64;
  const int pair = blockIdx.z >> 5, t = blockIdx.z & 31;
  const __nv_bfloat16* A = pair ? adjV : adjA;
  const __nv_bfloat16* Bm = pair ? sdA : sdV;
  const float* L = pair ? La : Lv;

  const char* Ab = (const char*)A + (long)t*2048 + (long)blockIdx.y * 128 * 65536;
  const char* Bb = (const char*)Bm + (long)t*2048 + (long)blockIdx.x * 256 * 65536;

  float acc[4][8][4];
  #pragma unroll
  for (int a=0;a<4;a++)
    #pragma unroll
    for (int b=0;b<8;b++)
      #pragma unroll
      for (int c=0;c<4;c++) acc[a][b][c]=0.f;

  g_main<16>(sbase, Ab, Bb, 65536, 65536, acc, tid, lane, wm, wn);

  const int tr = lane >> 2, tc = (lane & 3) * 2;
  const int batch = pair*T_ + t;
  float* dout = diag + (long)batch * B_;
  float rp[8];
  #pragma unroll
  for (int i=0;i<8;i++) rp[i]=0.f;
  #pragma unroll
  for (int mi=0; mi<4; ++mi){
    int rloc = wm + mi*16 + tr;
    int gi0 = blockIdx.y*128 + rloc;
    #pragma unroll
    for (int ni=0; ni<8; ++ni){
      int gj = blockIdx.x*256 + wn + ni*8 + tc;
      float L0 = L[(long)gj*T_ + t];
      float L1 = L[(long)(gj+1)*T_ + t];
      float* a = acc[mi][ni];
      float p00 = __expf(-a[0]-L0), p01 = __expf(-a[1]-L1);
      float p10 = __expf(-a[2]-L0), p11 = __expf(-a[3]-L1);
      rp[mi*2]   += p00 + p01;
      rp[mi*2+1] += p10 + p11;
      if (gj   == gi0)   dout[gi0]   = p00;
      if (gj+1 == gi0)   dout[gi0]   = p01;
      if (gj   == gi0+8) dout[gi0+8] = p10;
      if (gj+1 == gi0+8) dout[gi0+8] = p11;
    }
  }
  #pragma unroll
  for (int i=0;i<8;i++){
    rp[i] += __shfl_xor_sync(0xffffffffu, rp[i], 1);
    rp[i] += __shfl_xor_sync(0xffffffffu, rp[i], 2);
  }
  __syncthreads();                         // smem reuse safe point
  float* part = (float*)dsm;               // [128][4]
  int ng = warp & 3;
  if ((lane & 3) == 0){
    #pragma unroll
    for (int mi=0; mi<4; ++mi){
      int r = wm + mi*16 + tr;
      part[r*4 + ng]     = rp[mi*2];
      part[(r+8)*4 + ng] = rp[mi*2+1];
    }
  }
  __syncthreads();
  if (tid < 128){
    float s = part[tid*4] + part[tid*4+1] + part[tid*4+2] + part[tid*4+3];
    atomicAdd(&rowsum[(long)batch*B_ + blockIdx.y*128 + tid], s);
  }
}

// ---------------- loss partials and final mean ----------------
__global__ void k_loss2(const float* __restrict__ rs, const float* __restrict__ dg,
                        double* __restrict__ part){
  long base = (long)blockIdx.x * B_;
  float term = 0.f;
  #pragma unroll
  for (int h=0; h<2; ++h){
    long i = base + threadIdx.x + h*256;
    term += logf(rs[i]) - logf(dg[i]);
  }
  float s = blockSum(term);
  if (threadIdx.x == 0) part[blockIdx.x] = (double)s;
}
__global__ void k_final(const double* __restrict__ part, float* __restrict__ out){
  double s = (threadIdx.x < 64) ? part[threadIdx.x] : 0.0;
  #pragma unroll
  for (int o=16;o>0;o>>=1) s += __shfl_xor_sync(0xffffffffu, s, o);
  __shared__ double sm[2];
  if ((threadIdx.x & 31) == 0) sm[threadIdx.x>>5] = s;
  __syncthreads();
  if (threadIdx.x == 0) out[0] = (float)((sm[0]+sm[1]) / 32768.0);
}

// ---------------- launch ----------------
extern "C" void kernel_launch(void* const* d_in, const int* in_sizes, int n_in,
                              void* d_out, int out_size)
{
  const float* a = (const float*)d_in[0];
  const float* v = (const float*)d_in[1];
  const float* e = (const float*)d_in[2];
  float* out = (float*)d_out;

  __nv_bfloat16 *pa, *pv, *pe, *psa, *psv, *paa, *pav;
  float *pan, *pvn, *pen, *pLa, *pLv, *prs, *pdg;
  double *ppt;
  cudaGetSymbolAddress((void**)&pa,  g_a_bf);
  cudaGetSymbolAddress((void**)&pv,  g_v_bf);
  cudaGetSymbolAddress((void**)&pe,  g_e_bf);
  cudaGetSymbolAddress((void**)&pan, g_an);
  cudaGetSymbolAddress((void**)&pvn, g_vn);
  cudaGetSymbolAddress((void**)&pen, g_en);
  cudaGetSymbolAddress((void**)&psa, g_sd_a);
  cudaGetSymbolAddress((void**)&psv, g_sd_v);
  cudaGetSymbolAddress((void**)&paa, g_adj_a);
  cudaGetSymbolAddress((void**)&pav, g_adj_v);
  cudaGetSymbolAddress((void**)&pLa, g_L_a);
  cudaGetSymbolAddress((void**)&pLv, g_L_v);
  cudaGetSymbolAddress((void**)&prs, g_rowsum);
  cudaGetSymbolAddress((void**)&pdg, g_diag);
  cudaGetSymbolAddress((void**)&ppt, g_part);

  cudaFuncSetAttribute(k_g1, cudaFuncAttributeMaxDynamicSharedMemorySize, SMEM_DYN);
  cudaFuncSetAttribute(k_g2, cudaFuncAttributeMaxDynamicSharedMemorySize, SMEM_DYN);

  k_zero<<<64, 512>>>(prs);
  k_prep<<<(2*N_+M_)/8, 256>>>(a, v, e, pa, pv, pe, pan, pvn, pen);

  dim3 g1(M_/256, N_/128, 2);
  k_g1<<<g1, 256, SMEM_DYN>>>(pa, pv, pe, psa, psv, pan, pvn, pen);

  k_softmax2<<<2*N_, 256>>>(psa, psv, paa, pav, pLa, pLv);

  dim3 g2(B_/256, B_/128, 64);
  k_g2<<<g2, 256, SMEM_DYN>>>(paa, pav, psa, psv, pLa, pLv, prs, pdg);

  k_loss2<<<64, 256>>>(prs, pdg, ppt);
  k_final<<<1, 64>>>(ppt, out);
}